// round 1
// baseline (speedup 1.0000x reference)
#include <cuda_runtime.h>
#include <math.h>

#define NUM_L   4096
#define NTOT    8192
#define CC      768
#define HH      12
#define DDIM    64
#define KSEL    8
#define PPAT    256
#define NLAYERS 4
#define NEG_SLOPE 0.2f

// ---------------- device scratch (static: no allocation allowed) ----------------
__device__ float g_Lg[NUM_L * CC];
__device__ float g_Rg[NUM_L * CC];
__device__ float g_sim[NUM_L * NUM_L];          // 64 MB
__device__ int   g_idx[NUM_L * KSEL];
__device__ float g_x[NTOT * CC];
__device__ float g_z[NTOT * CC];
__device__ float g_xn[NTOT * CC];
__device__ float g_el[NTOT * HH];
__device__ float g_er[NTOT * HH];
__device__ float g_Wgt[CC * CC];
__device__ float g_Wst[NLAYERS * CC * CC];
__device__ int   g_deg[NUM_L];
__device__ int   g_off[NUM_L + 1];
__device__ int   g_elist[NUM_L * KSEL];

__device__ __forceinline__ float lrelu(float x) { return x >= 0.f ? x : NEG_SLOPE * x; }

// ---------------- NT SGEMM: C[M,N] = A[M,K] * B[N,K]^T ----------------
// M,N multiples of 128; K multiple of 16. 128x128 block tile, 8x8 per thread.
__global__ __launch_bounds__(256, 2) void sgemm_nt(
    const float* __restrict__ A, const float* __restrict__ B, float* __restrict__ Cmat,
    int M, int N, int K)
{
    __shared__ float As[16][128];
    __shared__ float Bs[16][128];
    const int tid  = threadIdx.x;
    const int bm   = blockIdx.y * 128;
    const int bn   = blockIdx.x * 128;
    const int tx   = tid & 15;        // 0..15 (n dir)
    const int ty   = tid >> 4;        // 0..15 (m dir)
    const int lrow = tid >> 2;        // 0..63
    const int lcol = (tid & 3) * 4;   // 0,4,8,12

    const float* Ap = A + (size_t)(bm + lrow) * K + lcol;
    const float* Bp = B + (size_t)(bn + lrow) * K + lcol;

    float acc[8][8];
#pragma unroll
    for (int i = 0; i < 8; i++)
#pragma unroll
        for (int j = 0; j < 8; j++) acc[i][j] = 0.f;

    for (int k0 = 0; k0 < K; k0 += 16) {
        float4 a0 = *(const float4*)(Ap + k0);
        float4 a1 = *(const float4*)(Ap + (size_t)64 * K + k0);
        float4 b0 = *(const float4*)(Bp + k0);
        float4 b1 = *(const float4*)(Bp + (size_t)64 * K + k0);
        __syncthreads();
        As[lcol + 0][lrow] = a0.x; As[lcol + 1][lrow] = a0.y;
        As[lcol + 2][lrow] = a0.z; As[lcol + 3][lrow] = a0.w;
        As[lcol + 0][lrow + 64] = a1.x; As[lcol + 1][lrow + 64] = a1.y;
        As[lcol + 2][lrow + 64] = a1.z; As[lcol + 3][lrow + 64] = a1.w;
        Bs[lcol + 0][lrow] = b0.x; Bs[lcol + 1][lrow] = b0.y;
        Bs[lcol + 2][lrow] = b0.z; Bs[lcol + 3][lrow] = b0.w;
        Bs[lcol + 0][lrow + 64] = b1.x; Bs[lcol + 1][lrow + 64] = b1.y;
        Bs[lcol + 2][lrow + 64] = b1.z; Bs[lcol + 3][lrow + 64] = b1.w;
        __syncthreads();
#pragma unroll
        for (int kk = 0; kk < 16; kk++) {
            float4 A0 = *(const float4*)&As[kk][ty * 4];
            float4 A1 = *(const float4*)&As[kk][ty * 4 + 64];
            float4 B0 = *(const float4*)&Bs[kk][tx * 4];
            float4 B1 = *(const float4*)&Bs[kk][tx * 4 + 64];
            float ar[8] = {A0.x, A0.y, A0.z, A0.w, A1.x, A1.y, A1.z, A1.w};
            float br[8] = {B0.x, B0.y, B0.z, B0.w, B1.x, B1.y, B1.z, B1.w};
#pragma unroll
            for (int i = 0; i < 8; i++)
#pragma unroll
                for (int j = 0; j < 8; j++) acc[i][j] = fmaf(ar[i], br[j], acc[i][j]);
        }
    }
#pragma unroll
    for (int i = 0; i < 8; i++) {
        int row = bm + ((i < 4) ? (ty * 4 + i) : (64 + ty * 4 + (i - 4)));
        float4 v0 = make_float4(acc[i][0], acc[i][1], acc[i][2], acc[i][3]);
        float4 v1 = make_float4(acc[i][4], acc[i][5], acc[i][6], acc[i][7]);
        *(float4*)(Cmat + (size_t)row * N + bn + tx * 4)      = v0;
        *(float4*)(Cmat + (size_t)row * N + bn + 64 + tx * 4) = v1;
    }
}

// ---------------- 768x768 transpose (Wt[j,k] = W[k,j]) ----------------
__global__ void transpose768(const float* __restrict__ src, float* __restrict__ dst) {
    __shared__ float t[32][33];
    int bx = blockIdx.x * 32, by = blockIdx.y * 32;
    int x = bx + threadIdx.x;
#pragma unroll
    for (int j = 0; j < 32; j += 8)
        t[threadIdx.y + j][threadIdx.x] = src[(size_t)(by + threadIdx.y + j) * CC + x];
    __syncthreads();
    int x2 = by + threadIdx.x;
#pragma unroll
    for (int j = 0; j < 32; j += 8)
        dst[(size_t)(bx + threadIdx.y + j) * CC + x2] = t[threadIdx.x][threadIdx.y + j];
}

// ---------------- top-8 per row of sim ----------------
__global__ __launch_bounds__(256) void topk8_kernel() {
    __shared__ float sv[NUM_L];
    __shared__ float rv[256];
    __shared__ int   ri[256];
    int r = blockIdx.x, tid = threadIdx.x;
    const float* row = g_sim + (size_t)r * NUM_L;
    for (int c = tid; c < NUM_L; c += 256) sv[c] = row[c];
    __syncthreads();
    for (int t = 0; t < KSEL; t++) {
        float bv = -INFINITY; int bi = NUM_L;
        for (int c = tid; c < NUM_L; c += 256) {
            float v = sv[c];
            if (v > bv || (v == bv && c < bi)) { bv = v; bi = c; }
        }
        rv[tid] = bv; ri[tid] = bi;
        __syncthreads();
        for (int s = 128; s > 0; s >>= 1) {
            if (tid < s) {
                float v = rv[tid + s]; int i2 = ri[tid + s];
                if (v > rv[tid] || (v == rv[tid] && i2 < ri[tid])) { rv[tid] = v; ri[tid] = i2; }
            }
            __syncthreads();
        }
        if (tid == 0) { g_idx[r * KSEL + t] = ri[0]; sv[ri[0]] = -INFINITY; }
        __syncthreads();
    }
}

// ---------------- CSR build (dst-grouped, deterministic) ----------------
__global__ void zero_deg_kernel() {
    int i = blockIdx.x * 256 + threadIdx.x;
    if (i < NUM_L) g_deg[i] = 0;
}
__global__ void count_deg_kernel() {
    int e = blockIdx.x * 256 + threadIdx.x;
    if (e < NUM_L * KSEL) atomicAdd(&g_deg[g_idx[e]], 1);
}
__global__ __launch_bounds__(512) void scan_off_kernel() {
    __shared__ int ss[512];
    int tid = threadIdx.x;
    int base = tid * 8;
    int loc[8]; int s = 0;
#pragma unroll
    for (int i = 0; i < 8; i++) { loc[i] = s; s += g_deg[base + i]; }
    ss[tid] = s; __syncthreads();
    for (int d = 1; d < 512; d <<= 1) {
        int v = (tid >= d) ? ss[tid - d] : 0;
        __syncthreads();
        ss[tid] += v;
        __syncthreads();
    }
    int excl = ss[tid] - s;
#pragma unroll
    for (int i = 0; i < 8; i++) g_off[base + i] = excl + loc[i];
    if (tid == 511) g_off[NUM_L] = ss[511];
}
// one thread per dst scans all 32768 edges in fixed order -> deterministic CSR
__global__ void fill_elist_kernel() {
    int j = blockIdx.x * 256 + threadIdx.x;
    if (j >= NUM_L) return;
    int w = g_off[j];
#pragma unroll 4
    for (int e = 0; e < NUM_L * KSEL; e++) {
        if (g_idx[e] == j) g_elist[w++] = e >> 3;   // src left node
    }
}

// ---------------- x init: concat(node_l, node_r) ----------------
__global__ void init_x_kernel(const float* __restrict__ l, const float* __restrict__ r) {
    int i = blockIdx.x * 256 + threadIdx.x;
    if (i < NUM_L * CC) { g_x[i] = l[i]; g_x[NUM_L * CC + i] = r[i]; }
}

// ---------------- el/er: per-node per-head dot with a_src/a_dst ----------------
__global__ __launch_bounds__(384) void elr_kernel(const float* __restrict__ as,
                                                  const float* __restrict__ ad) {
    int n = blockIdx.x;
    int w = threadIdx.x >> 5, lane = threadIdx.x & 31;
    const float* zr = g_z + (size_t)n * CC + w * DDIM;
    float z0 = zr[lane], z1 = zr[lane + 32];
    float sl = z0 * as[w * DDIM + lane] + z1 * as[w * DDIM + lane + 32];
    float sr = z0 * ad[w * DDIM + lane] + z1 * ad[w * DDIM + lane + 32];
#pragma unroll
    for (int o = 16; o; o >>= 1) {
        sl += __shfl_xor_sync(0xffffffffu, sl, o);
        sr += __shfl_xor_sync(0xffffffffu, sr, o);
    }
    if (lane == 0) { g_el[n * HH + w] = sl; g_er[n * HH + w] = sr; }
}

// ---------------- 12-channel block reductions (blockDim == 256) ----------------
__device__ __forceinline__ void block_max12(float* lv, float* red, float* outp, int tid) {
#pragma unroll
    for (int h = 0; h < HH; h++)
#pragma unroll
        for (int o = 16; o; o >>= 1)
            lv[h] = fmaxf(lv[h], __shfl_xor_sync(0xffffffffu, lv[h], o));
    if ((tid & 31) == 0) {
#pragma unroll
        for (int h = 0; h < HH; h++) red[(tid >> 5) * HH + h] = lv[h];
    }
    __syncthreads();
    if (tid < HH) {
        float v = red[tid];
#pragma unroll
        for (int w = 1; w < 8; w++) v = fmaxf(v, red[w * HH + tid]);
        outp[tid] = v;
    }
    __syncthreads();
}
__device__ __forceinline__ void block_sum12(float* lv, float* red, float* outp, int tid) {
#pragma unroll
    for (int h = 0; h < HH; h++)
#pragma unroll
        for (int o = 16; o; o >>= 1)
            lv[h] += __shfl_xor_sync(0xffffffffu, lv[h], o);
    if ((tid & 31) == 0) {
#pragma unroll
        for (int h = 0; h < HH; h++) red[(tid >> 5) * HH + h] = lv[h];
    }
    __syncthreads();
    if (tid < HH) {
        float v = red[tid];
#pragma unroll
        for (int w = 1; w < 8; w++) v += red[w * HH + tid];
        outp[tid] = v;
    }
    __syncthreads();
}

// ---------------- GAT aggregation, graph 1 (top-K + self loops) ----------------
__global__ __launch_bounds__(256) void agg1_kernel() {
    int n = blockIdx.x, tid = threadIdx.x;
    if (n < NUM_L) {  // left nodes: self loop only -> out = z
        for (int d = tid; d < CC; d += 256) g_xn[(size_t)n * CC + d] = g_z[(size_t)n * CC + d];
        return;
    }
    __shared__ float s_er[HH], s_m[HH], s_sum[HH], s_inv[HH];
    __shared__ float red[8 * HH];
    int j = n - NUM_L;
    int e0 = g_off[j], e1 = g_off[j + 1];
    int deg = e1 - e0;
    if (tid < HH) s_er[tid] = g_er[n * HH + tid];
    __syncthreads();

    float lv[HH];
#pragma unroll
    for (int h = 0; h < HH; h++) lv[h] = -INFINITY;
    for (int t = tid; t < deg + 1; t += 256) {           // +1 = self edge
        int src = (t < deg) ? g_elist[e0 + t] : n;
        const float* elp = g_el + src * HH;
#pragma unroll
        for (int h = 0; h < HH; h++) lv[h] = fmaxf(lv[h], lrelu(elp[h] + s_er[h]));
    }
    block_max12(lv, red, s_m, tid);

#pragma unroll
    for (int h = 0; h < HH; h++) lv[h] = 0.f;
    for (int t = tid; t < deg + 1; t += 256) {
        int src = (t < deg) ? g_elist[e0 + t] : n;
        const float* elp = g_el + src * HH;
#pragma unroll
        for (int h = 0; h < HH; h++) lv[h] += expf(lrelu(elp[h] + s_er[h]) - s_m[h]);
    }
    block_sum12(lv, red, s_sum, tid);
    if (tid < HH) s_inv[tid] = 1.f / s_sum[tid];
    __syncthreads();

    for (int d = tid; d < CC; d += 256) {
        int h = d >> 6;
        float m = s_m[h], inv = s_inv[h], erh = s_er[h];
        float acc = expf(lrelu(g_el[n * HH + h] + erh) - m) * inv * g_z[(size_t)n * CC + d];
        for (int e = e0; e < e1; e++) {
            int src = g_elist[e];
            acc += expf(lrelu(g_el[src * HH + h] + erh) - m) * inv * g_z[(size_t)src * CC + d];
        }
        g_xn[(size_t)n * CC + d] = acc;
    }
}

// ---------------- GAT aggregation, graph 2 (patch->image + self loops) -------
// img nodes (n % 256 == 0) receive 256 patch edges + a DUPLICATE self loop
// (the (img,img) edge appears both in the gather edges and in the self loops),
// reproduced exactly as a 2x weight on src == img.
__global__ __launch_bounds__(256) void agg2_kernel() {
    int n = blockIdx.x, tid = threadIdx.x;
    if (n & (PPAT - 1)) {  // non-image nodes: self loop only -> out = z
        for (int d = tid; d < CC; d += 256) g_xn[(size_t)n * CC + d] = g_z[(size_t)n * CC + d];
        return;
    }
    __shared__ float s_er[HH], s_m[HH], s_sum[HH], s_inv[HH];
    __shared__ float s_w[PPAT * HH];
    __shared__ float red[8 * HH];
    if (tid < HH) s_er[tid] = g_er[n * HH + tid];
    __syncthreads();

    int src = n + tid;
    float ev[HH];
    const float* elp = g_el + src * HH;
#pragma unroll
    for (int h = 0; h < HH; h++) ev[h] = lrelu(elp[h] + s_er[h]);

    float lv[HH];
#pragma unroll
    for (int h = 0; h < HH; h++) lv[h] = ev[h];
    block_max12(lv, red, s_m, tid);

    float mult = (tid == 0) ? 2.f : 1.f;   // duplicated self edge
    float ex[HH];
#pragma unroll
    for (int h = 0; h < HH; h++) { ex[h] = expf(ev[h] - s_m[h]) * mult; lv[h] = ex[h]; }
    block_sum12(lv, red, s_sum, tid);
    if (tid < HH) s_inv[tid] = 1.f / s_sum[tid];
    __syncthreads();
#pragma unroll
    for (int h = 0; h < HH; h++) s_w[tid * HH + h] = ex[h] * s_inv[h];
    __syncthreads();

    for (int d = tid; d < CC; d += 256) {
        int h = d >> 6;
        float acc = 0.f;
        for (int i = 0; i < PPAT; i++)
            acc += s_w[i * HH + h] * g_z[(size_t)(n + i) * CC + d];
        g_xn[(size_t)n * CC + d] = acc;
    }
}

// ---------------- bias + activation ----------------
__global__ void act_kernel(const float* __restrict__ b, int elu) {
    int i = blockIdx.x * 256 + threadIdx.x;   // grid sized exactly NTOT*CC/256
    float v = g_xn[i] + b[i % CC];
    if (elu) v = v > 0.f ? v : expm1f(v);
    g_x[i] = v;
}

// ---------------- output: x[img_node] ----------------
__global__ void extract_kernel(float* __restrict__ out) {
    int i = blockIdx.x * 256 + threadIdx.x;   // 32*768 = 24576 = 96 blocks
    int r = i / CC, c = i % CC;
    out[i] = g_x[(size_t)(r * PPAT) * CC + c];
}

// ---------------- launch ----------------
extern "C" void kernel_launch(void* const* d_in, const int* in_sizes, int n_in,
                              void* d_out, int out_size) {
    (void)in_sizes; (void)n_in; (void)out_size;
    const float* l_feat = (const float*)d_in[0];
    const float* r_feat = (const float*)d_in[1];
    const float* Wg     = (const float*)d_in[2];
    const float* Ws     = (const float*)d_in[3];
    const float* a_src  = (const float*)d_in[4];
    const float* a_dst  = (const float*)d_in[5];
    const float* b      = (const float*)d_in[6];
    float* out = (float*)d_out;

    float *pLg, *pRg, *pSim, *pX, *pZ, *pWgt, *pWst;
    cudaGetSymbolAddress((void**)&pLg,  g_Lg);
    cudaGetSymbolAddress((void**)&pRg,  g_Rg);
    cudaGetSymbolAddress((void**)&pSim, g_sim);
    cudaGetSymbolAddress((void**)&pX,   g_x);
    cudaGetSymbolAddress((void**)&pZ,   g_z);
    cudaGetSymbolAddress((void**)&pWgt, g_Wgt);
    cudaGetSymbolAddress((void**)&pWst, g_Wst);

    dim3 tb(32, 8), tg(24, 24);
    transpose768<<<tg, tb>>>(Wg, pWgt);
    for (int l = 0; l < NLAYERS; l++)
        transpose768<<<tg, tb>>>(Ws + (size_t)l * CC * CC, pWst + (size_t)l * CC * CC);

    // GraphGenerator
    sgemm_nt<<<dim3(CC / 128, NUM_L / 128), 256>>>(l_feat, pWgt, pLg, NUM_L, CC, CC);
    sgemm_nt<<<dim3(CC / 128, NUM_L / 128), 256>>>(r_feat, pWgt, pRg, NUM_L, CC, CC);
    sgemm_nt<<<dim3(NUM_L / 128, NUM_L / 128), 256>>>(pLg, pRg, pSim, NUM_L, NUM_L, CC);
    topk8_kernel<<<NUM_L, 256>>>();

    // CSR for graph 1
    zero_deg_kernel<<<16, 256>>>();
    count_deg_kernel<<<NUM_L * KSEL / 256, 256>>>();
    scan_off_kernel<<<1, 512>>>();
    fill_elist_kernel<<<16, 256>>>();

    init_x_kernel<<<NUM_L * CC / 256, 256>>>(l_feat, r_feat);

    for (int g = 0; g < 2; g++) {
        for (int l = 0; l < NLAYERS; l++) {
            sgemm_nt<<<dim3(CC / 128, NTOT / 128), 256>>>(
                pX, pWst + (size_t)l * CC * CC, pZ, NTOT, CC, CC);
            elr_kernel<<<NTOT, 384>>>(a_src + l * HH * DDIM, a_dst + l * HH * DDIM);
            if (g == 0) agg1_kernel<<<NTOT, 256>>>();
            else        agg2_kernel<<<NTOT, 256>>>();
            act_kernel<<<NTOT * CC / 256, 256>>>(b + l * CC, (l < NLAYERS - 1) ? 1 : 0);
        }
    }
    extract_kernel<<<96, 256>>>(out);
}

// round 4
// speedup vs baseline: 2.6754x; 2.6754x over previous
#include <cuda_runtime.h>
#include <cuda_bf16.h>
#include <math.h>
#include <stdint.h>

#define NUM_L   4096
#define NTOT    8192
#define CC      768
#define HH      12
#define DDIM    64
#define KSEL    8
#define PPAT    256
#define NLAYERS 4
#define NEG_SLOPE 0.2f

// ---------------- device scratch (static: no allocation allowed) ----------------
__device__ float g_sim[NUM_L * NUM_L];          // 64 MB
__device__ int   g_idx[NUM_L * KSEL];
__device__ float g_x [NTOT * CC];
__device__ float g_z [NTOT * CC];
__device__ float g_xn[NTOT * CC];
__device__ float g_el[NTOT * HH];
__device__ float g_er[NTOT * HH];
__device__ float g_Lg[NUM_L * CC];
__device__ float g_Rg[NUM_L * CC];
__device__ __nv_bfloat16 g_xh[NTOT * CC], g_xl[NTOT * CC];
__device__ __nv_bfloat16 g_Wgt_h[CC * CC], g_Wgt_l[CC * CC];
__device__ __nv_bfloat16 g_Wst_h[NLAYERS * CC * CC], g_Wst_l[NLAYERS * CC * CC];
__device__ __nv_bfloat16 g_Lgh[NUM_L * CC], g_Lgl[NUM_L * CC];
__device__ __nv_bfloat16 g_Rgh[NUM_L * CC], g_Rgl[NUM_L * CC];
__device__ int   g_deg[NUM_L];
__device__ int   g_off[NUM_L + 1];
__device__ int   g_elist[NUM_L * KSEL];

__device__ __forceinline__ float lrelu(float x) { return x >= 0.f ? x : NEG_SLOPE * x; }

__device__ __forceinline__ uint32_t smem_u32(const void* p) {
    uint32_t a;
    asm("{ .reg .u64 t; cvta.to.shared.u64 t, %1; cvt.u32.u64 %0, t; }" : "=r"(a) : "l"(p));
    return a;
}

// ======================= mma.sync bf16x3 GEMM =======================
// C[M,N] = fp32(A) * fp32(B)^T.  A,B as bf16 (hi,lo) pairs, K-contiguous rows.
// CTA tile 128x128, 256 thr (8 warps, 2x4), warp tile 64x32, K-chunk 32, 3 stages.
#define SA      40                      // smem row stride in bf16 (80 B, ldmatrix conflict-free)
#define TILE_B  (128 * SA * 2)          // 10240 B per 128x32 tile
#define STAGE_B (4 * TILE_B)            // Ah, Al, Bh, Bl = 40960 B
#define NSTAGE  3
#define GEMM_SMEM (NSTAGE * STAGE_B)    // 122880 B

#define CP16(s, g) \
    asm volatile("cp.async.cg.shared.global [%0], [%1], 16;" :: "r"(s), "l"(g))
#define CP_COMMIT() asm volatile("cp.async.commit_group;" ::: "memory")
#define CP_WAIT1()  asm volatile("cp.async.wait_group 1;" ::: "memory")

#define LDSM4(r0, r1, r2, r3, a) \
    asm volatile("ldmatrix.sync.aligned.m8n8.x4.shared.b16 {%0,%1,%2,%3}, [%4];" \
                 : "=r"(r0), "=r"(r1), "=r"(r2), "=r"(r3) : "r"(a))

#define MMA16816(d, a, b) \
    asm volatile("mma.sync.aligned.m16n8k16.row.col.f32.bf16.bf16.f32 " \
                 "{%0,%1,%2,%3},{%4,%5,%6,%7},{%8,%9},{%0,%1,%2,%3};" \
                 : "+f"((d)[0]), "+f"((d)[1]), "+f"((d)[2]), "+f"((d)[3]) \
                 : "r"((a)[0]), "r"((a)[1]), "r"((a)[2]), "r"((a)[3]), \
                   "r"((b)[0]), "r"((b)[1]))

__global__ void __launch_bounds__(256, 1) gemm_mma_bf16x3(
    const __nv_bfloat16* __restrict__ Ah, const __nv_bfloat16* __restrict__ Al,
    const __nv_bfloat16* __restrict__ Bh, const __nv_bfloat16* __restrict__ Bl,
    float* __restrict__ C, int M, int N, int K)
{
    extern __shared__ __align__(16) char dsm[];
    const uint32_t sbase = smem_u32(dsm);
    const int tid = threadIdx.x;
    const int wid = tid >> 5, lane = tid & 31;
    const int wm = wid & 1, wn = wid >> 1;          // 2 x 4 warp grid
    const int bm = blockIdx.y * 128, bn = blockIdx.x * 128;

    const __nv_bfloat16* srcs[4] = {
        Ah + (size_t)bm * K, Al + (size_t)bm * K,
        Bh + (size_t)bn * K, Bl + (size_t)bn * K };

    // per-thread load mapping: 2 segments of 16B per tile per stage
    const int r0 = tid >> 2, c0 = tid & 3;          // seg 0: row, 16B-col
    const int r1 = (tid + 256) >> 2, c1 = (tid + 256) & 3;

    // ldmatrix per-thread offsets
    const int lj = lane >> 3, lr = lane & 7;
    const uint32_t aoff = (uint32_t)((((lj & 1) * 8 + lr) * SA + (lj >> 1) * 8) * 2);
    const uint32_t boff = (uint32_t)((((lj >> 1) * 8 + lr) * SA + (lj & 1) * 8) * 2);

    float acc[4][4][4];
#pragma unroll
    for (int i = 0; i < 4; i++)
#pragma unroll
        for (int j = 0; j < 4; j++)
#pragma unroll
            for (int k = 0; k < 4; k++) acc[i][j][k] = 0.f;

    const int nc = K >> 5;                          // K-chunks of 32

    // prologue: stages 0 and 1
#pragma unroll
    for (int s = 0; s < NSTAGE - 1; s++) {
        const uint32_t st = sbase + s * STAGE_B;
        const int kb = s * 32;
#pragma unroll
        for (int t = 0; t < 4; t++) {
            const __nv_bfloat16* gp = srcs[t] + kb;
            CP16(st + t * TILE_B + r0 * (SA * 2) + c0 * 16, gp + (size_t)r0 * K + c0 * 8);
            CP16(st + t * TILE_B + r1 * (SA * 2) + c1 * 16, gp + (size_t)r1 * K + c1 * 8);
        }
        CP_COMMIT();
    }

    for (int c = 0; c < nc; c++) {
        CP_WAIT1();
        __syncthreads();
        const uint32_t st = sbase + (c % NSTAGE) * STAGE_B;
        const uint32_t sAh = st + 0 * TILE_B + (uint32_t)(wm * 64 * SA * 2);
        const uint32_t sAl = st + 1 * TILE_B + (uint32_t)(wm * 64 * SA * 2);
        const uint32_t sBh = st + 2 * TILE_B + (uint32_t)(wn * 32 * SA * 2);
        const uint32_t sBl = st + 3 * TILE_B + (uint32_t)(wn * 32 * SA * 2);
#pragma unroll
        for (int kk = 0; kk < 2; kk++) {
            uint32_t ah[4][4], al[4][4], bh[2][4], bl[2][4];
            const uint32_t kadd = kk * 32;          // kk*16 elems * 2 B
#pragma unroll
            for (int mt = 0; mt < 4; mt++) {
                const uint32_t moff = (uint32_t)(mt * 16 * SA * 2) + kadd;
                LDSM4(ah[mt][0], ah[mt][1], ah[mt][2], ah[mt][3], sAh + moff + aoff);
                LDSM4(al[mt][0], al[mt][1], al[mt][2], al[mt][3], sAl + moff + aoff);
            }
#pragma unroll
            for (int np = 0; np < 2; np++) {
                const uint32_t noff = (uint32_t)(np * 16 * SA * 2) + kadd;
                LDSM4(bh[np][0], bh[np][1], bh[np][2], bh[np][3], sBh + noff + boff);
                LDSM4(bl[np][0], bl[np][1], bl[np][2], bl[np][3], sBl + noff + boff);
            }
#pragma unroll
            for (int mt = 0; mt < 4; mt++)
#pragma unroll
                for (int nt = 0; nt < 4; nt++) {
                    const uint32_t* bhf = &bh[nt >> 1][(nt & 1) * 2];
                    const uint32_t* blf = &bl[nt >> 1][(nt & 1) * 2];
                    MMA16816(acc[mt][nt], ah[mt], bhf);
                    MMA16816(acc[mt][nt], ah[mt], blf);
                    MMA16816(acc[mt][nt], al[mt], bhf);
                }
        }
        __syncthreads();
        if (c + NSTAGE - 1 < nc) {
            const uint32_t st2 = sbase + ((c + NSTAGE - 1) % NSTAGE) * STAGE_B;
            const int kb = (c + NSTAGE - 1) * 32;
#pragma unroll
            for (int t = 0; t < 4; t++) {
                const __nv_bfloat16* gp = srcs[t] + kb;
                CP16(st2 + t * TILE_B + r0 * (SA * 2) + c0 * 16, gp + (size_t)r0 * K + c0 * 8);
                CP16(st2 + t * TILE_B + r1 * (SA * 2) + c1 * 16, gp + (size_t)r1 * K + c1 * 8);
            }
        }
        CP_COMMIT();
    }

    // epilogue: d-frag thread t -> rows lane/4 and lane/4+8, cols (lane%4)*2,+1
    const int er = lane >> 2, ec = (lane & 3) * 2;
#pragma unroll
    for (int mt = 0; mt < 4; mt++) {
        const int row = bm + wm * 64 + mt * 16 + er;
#pragma unroll
        for (int nt = 0; nt < 4; nt++) {
            const int col = bn + wn * 32 + nt * 8 + ec;
            float2* p0 = (float2*)(C + (size_t)row * N + col);
            float2* p1 = (float2*)(C + (size_t)(row + 8) * N + col);
            *p0 = make_float2(acc[mt][nt][0], acc[mt][nt][1]);
            *p1 = make_float2(acc[mt][nt][2], acc[mt][nt][3]);
        }
    }
}

// ======================= fp32 -> bf16 hi/lo split =======================
__device__ __forceinline__ void split2(float v, __nv_bfloat16& h, __nv_bfloat16& l) {
    h = __float2bfloat16(v);
    l = __float2bfloat16(v - __bfloat162float(h));
}
__global__ void split_kernel(const float* __restrict__ src, __nv_bfloat16* __restrict__ h,
                             __nv_bfloat16* __restrict__ l, int n) {
    int i = blockIdx.x * 256 + threadIdx.x;
    if (i < n) split2(src[i], h[i], l[i]);
}

// ---------------- 768x768 transpose + split ----------------
__global__ void transpose_split768(const float* __restrict__ src,
                                   __nv_bfloat16* __restrict__ dh,
                                   __nv_bfloat16* __restrict__ dl) {
    __shared__ float t[32][33];
    int bx = blockIdx.x * 32, by = blockIdx.y * 32;
    int x = bx + threadIdx.x;
#pragma unroll
    for (int j = 0; j < 32; j += 8)
        t[threadIdx.y + j][threadIdx.x] = src[(size_t)(by + threadIdx.y + j) * CC + x];
    __syncthreads();
    int x2 = by + threadIdx.x;
#pragma unroll
    for (int j = 0; j < 32; j += 8) {
        float v = t[threadIdx.x][threadIdx.y + j];
        size_t o = (size_t)(bx + threadIdx.y + j) * CC + x2;
        __nv_bfloat16 h, l; split2(v, h, l);
        dh[o] = h; dl[o] = l;
    }
}

// ---------------- top-8 per row of sim ----------------
__global__ __launch_bounds__(256) void topk8_kernel() {
    __shared__ float sv[NUM_L];
    __shared__ float rv[256];
    __shared__ int   ri[256];
    int r = blockIdx.x, tid = threadIdx.x;
    const float* row = g_sim + (size_t)r * NUM_L;
    for (int c = tid; c < NUM_L; c += 256) sv[c] = row[c];
    __syncthreads();
    for (int t = 0; t < KSEL; t++) {
        float bv = -INFINITY; int bi = NUM_L;
        for (int c = tid; c < NUM_L; c += 256) {
            float v = sv[c];
            if (v > bv || (v == bv && c < bi)) { bv = v; bi = c; }
        }
        rv[tid] = bv; ri[tid] = bi;
        __syncthreads();
        for (int s = 128; s > 0; s >>= 1) {
            if (tid < s) {
                float v = rv[tid + s]; int i2 = ri[tid + s];
                if (v > rv[tid] || (v == rv[tid] && i2 < ri[tid])) { rv[tid] = v; ri[tid] = i2; }
            }
            __syncthreads();
        }
        if (tid == 0) { g_idx[r * KSEL + t] = ri[0]; sv[ri[0]] = -INFINITY; }
        __syncthreads();
    }
}

// ---------------- CSR build (dst-grouped; edge order restored by sort) ---------
__global__ void zero_deg_kernel() {
    int i = blockIdx.x * 256 + threadIdx.x;
    if (i < NUM_L) g_deg[i] = 0;
}
__global__ void count_deg_kernel() {
    int e = blockIdx.x * 256 + threadIdx.x;
    if (e < NUM_L * KSEL) atomicAdd(&g_deg[g_idx[e]], 1);
}
__global__ __launch_bounds__(512) void scan_off_kernel() {
    __shared__ int ss[512];
    int tid = threadIdx.x;
    int base = tid * 8;
    int loc[8]; int s = 0;
#pragma unroll
    for (int i = 0; i < 8; i++) { loc[i] = s; s += g_deg[base + i]; }
    ss[tid] = s; __syncthreads();
    for (int d = 1; d < 512; d <<= 1) {
        int v = (tid >= d) ? ss[tid - d] : 0;
        __syncthreads();
        ss[tid] += v;
        __syncthreads();
    }
    int excl = ss[tid] - s;
#pragma unroll
    for (int i = 0; i < 8; i++) g_off[base + i] = excl + loc[i];
    if (tid == 511) g_off[NUM_L] = ss[511];
}
__global__ void init_cursor_kernel() {
    int i = blockIdx.x * 256 + threadIdx.x;
    if (i < NUM_L) g_deg[i] = g_off[i];
}
__global__ void fill_atomic_kernel() {
    int e = blockIdx.x * 256 + threadIdx.x;
    if (e < NUM_L * KSEL) {
        int pos = atomicAdd(&g_deg[g_idx[e]], 1);
        g_elist[pos] = e;                 // store edge index; sorted below
    }
}
__global__ void sort_convert_kernel() {
    int j = blockIdx.x * 256 + threadIdx.x;
    if (j >= NUM_L) return;
    int e0 = g_off[j], e1 = g_off[j + 1];
    for (int i = e0 + 1; i < e1; i++) {   // insertion sort by edge index (deterministic)
        int key = g_elist[i];
        int k = i - 1;
        while (k >= e0 && g_elist[k] > key) { g_elist[k + 1] = g_elist[k]; k--; }
        g_elist[k + 1] = key;
    }
    for (int i = e0; i < e1; i++) g_elist[i] >>= 3;   // edge -> src left node
}

// ---------------- x init: concat(node_l, node_r) + split ----------------
__global__ void init_x_kernel(const float* __restrict__ l, const float* __restrict__ r) {
    int i = blockIdx.x * 256 + threadIdx.x;
    if (i < NUM_L * CC) {
        float a = l[i], b = r[i];
        g_x[i] = a; g_x[NUM_L * CC + i] = b;
        split2(a, g_xh[i], g_xl[i]);
        split2(b, g_xh[NUM_L * CC + i], g_xl[NUM_L * CC + i]);
    }
}

// ---------------- el/er ----------------
__global__ __launch_bounds__(384) void elr_kernel(const float* __restrict__ as,
                                                  const float* __restrict__ ad) {
    int n = blockIdx.x;
    int w = threadIdx.x >> 5, lane = threadIdx.x & 31;
    const float* zr = g_z + (size_t)n * CC + w * DDIM;
    float z0 = zr[lane], z1 = zr[lane + 32];
    float sl = z0 * as[w * DDIM + lane] + z1 * as[w * DDIM + lane + 32];
    float sr = z0 * ad[w * DDIM + lane] + z1 * ad[w * DDIM + lane + 32];
#pragma unroll
    for (int o = 16; o; o >>= 1) {
        sl += __shfl_xor_sync(0xffffffffu, sl, o);
        sr += __shfl_xor_sync(0xffffffffu, sr, o);
    }
    if (lane == 0) { g_el[n * HH + w] = sl; g_er[n * HH + w] = sr; }
}

// ---------------- 12-channel block reductions ----------------
__device__ __forceinline__ void block_max12(float* lv, float* red, float* outp, int tid) {
#pragma unroll
    for (int h = 0; h < HH; h++)
#pragma unroll
        for (int o = 16; o; o >>= 1)
            lv[h] = fmaxf(lv[h], __shfl_xor_sync(0xffffffffu, lv[h], o));
    if ((tid & 31) == 0)
#pragma unroll
        for (int h = 0; h < HH; h++) red[(tid >> 5) * HH + h] = lv[h];
    __syncthreads();
    if (tid < HH) {
        float v = red[tid];
#pragma unroll
        for (int w = 1; w < 8; w++) v = fmaxf(v, red[w * HH + tid]);
        outp[tid] = v;
    }
    __syncthreads();
}
__device__ __forceinline__ void block_sum12(float* lv, float* red, float* outp, int tid) {
#pragma unroll
    for (int h = 0; h < HH; h++)
#pragma unroll
        for (int o = 16; o; o >>= 1)
            lv[h] += __shfl_xor_sync(0xffffffffu, lv[h], o);
    if ((tid & 31) == 0)
#pragma unroll
        for (int h = 0; h < HH; h++) red[(tid >> 5) * HH + h] = lv[h];
    __syncthreads();
    if (tid < HH) {
        float v = red[tid];
#pragma unroll
        for (int w = 1; w < 8; w++) v += red[w * HH + tid];
        outp[tid] = v;
    }
    __syncthreads();
}

// ---------------- GAT aggregation, graph 1 ----------------
__global__ __launch_bounds__(256) void agg1_kernel() {
    int n = blockIdx.x, tid = threadIdx.x;
    if (n < NUM_L) {
        for (int d = tid; d < CC; d += 256) g_xn[(size_t)n * CC + d] = g_z[(size_t)n * CC + d];
        return;
    }
    __shared__ float s_er[HH], s_m[HH], s_sum[HH], s_inv[HH];
    __shared__ float red[8 * HH];
    int j = n - NUM_L;
    int e0 = g_off[j], e1 = g_off[j + 1];
    int deg = e1 - e0;
    if (tid < HH) s_er[tid] = g_er[n * HH + tid];
    __syncthreads();

    float lv[HH];
#pragma unroll
    for (int h = 0; h < HH; h++) lv[h] = -INFINITY;
    for (int t = tid; t < deg + 1; t += 256) {
        int src = (t < deg) ? g_elist[e0 + t] : n;
        const float* elp = g_el + src * HH;
#pragma unroll
        for (int h = 0; h < HH; h++) lv[h] = fmaxf(lv[h], lrelu(elp[h] + s_er[h]));
    }
    block_max12(lv, red, s_m, tid);

#pragma unroll
    for (int h = 0; h < HH; h++) lv[h] = 0.f;
    for (int t = tid; t < deg + 1; t += 256) {
        int src = (t < deg) ? g_elist[e0 + t] : n;
        const float* elp = g_el + src * HH;
#pragma unroll
        for (int h = 0; h < HH; h++) lv[h] += expf(lrelu(elp[h] + s_er[h]) - s_m[h]);
    }
    block_sum12(lv, red, s_sum, tid);
    if (tid < HH) s_inv[tid] = 1.f / s_sum[tid];
    __syncthreads();

    for (int d = tid; d < CC; d += 256) {
        int h = d >> 6;
        float m = s_m[h], inv = s_inv[h], erh = s_er[h];
        float acc = expf(lrelu(g_el[n * HH + h] + erh) - m) * inv * g_z[(size_t)n * CC + d];
        for (int e = e0; e < e1; e++) {
            int src = g_elist[e];
            acc += expf(lrelu(g_el[src * HH + h] + erh) - m) * inv * g_z[(size_t)src * CC + d];
        }
        g_xn[(size_t)n * CC + d] = acc;
    }
}

// ---------------- GAT aggregation, graph 2 ----------------
__global__ __launch_bounds__(256) void agg2_kernel() {
    int n = blockIdx.x, tid = threadIdx.x;
    if (n & (PPAT - 1)) {
        for (int d = tid; d < CC; d += 256) g_xn[(size_t)n * CC + d] = g_z[(size_t)n * CC + d];
        return;
    }
    __shared__ float s_er[HH], s_m[HH], s_sum[HH], s_inv[HH];
    __shared__ float s_w[PPAT * HH];
    __shared__ float red[8 * HH];
    if (tid < HH) s_er[tid] = g_er[n * HH + tid];
    __syncthreads();

    int src = n + tid;
    float ev[HH];
    const float* elp = g_el + src * HH;
#pragma unroll
    for (int h = 0; h < HH; h++) ev[h] = lrelu(elp[h] + s_er[h]);

    float lv[HH];
#pragma unroll
    for (int h = 0; h < HH; h++) lv[h] = ev[h];
    block_max12(lv, red, s_m, tid);

    float mult = (tid == 0) ? 2.f : 1.f;   // duplicated self edge
    float ex[HH];
#pragma unroll
    for (int h = 0; h < HH; h++) { ex[h] = expf(ev[h] - s_m[h]) * mult; lv[h] = ex[h]; }
    block_sum12(lv, red, s_sum, tid);
    if (tid < HH) s_inv[tid] = 1.f / s_sum[tid];
    __syncthreads();
#pragma unroll
    for (int h = 0; h < HH; h++) s_w[tid * HH + h] = ex[h] * s_inv[h];
    __syncthreads();

    for (int d = tid; d < CC; d += 256) {
        int h = d >> 6;
        float acc = 0.f;
        for (int i = 0; i < PPAT; i++)
            acc += s_w[i * HH + h] * g_z[(size_t)(n + i) * CC + d];
        g_xn[(size_t)n * CC + d] = acc;
    }
}

// ---------------- bias + activation (+ bf16 split for next GEMM) ----------------
__global__ void act_kernel(const float* __restrict__ b, int elu) {
    int i = blockIdx.x * 256 + threadIdx.x;
    float v = g_xn[i] + b[i % CC];
    if (elu) v = v > 0.f ? v : expm1f(v);
    g_x[i] = v;
    split2(v, g_xh[i], g_xl[i]);
}

// ---------------- output ----------------
__global__ void extract_kernel(float* __restrict__ out) {
    int i = blockIdx.x * 256 + threadIdx.x;
    int r = i / CC, c = i % CC;
    out[i] = g_x[(size_t)(r * PPAT) * CC + c];
}

// ---------------- launch ----------------
extern "C" void kernel_launch(void* const* d_in, const int* in_sizes, int n_in,
                              void* d_out, int out_size) {
    (void)in_sizes; (void)n_in; (void)out_size;
    const float* l_feat = (const float*)d_in[0];
    const float* r_feat = (const float*)d_in[1];
    const float* Wg     = (const float*)d_in[2];
    const float* Ws     = (const float*)d_in[3];
    const float* a_src  = (const float*)d_in[4];
    const float* a_dst  = (const float*)d_in[5];
    const float* b      = (const float*)d_in[6];
    float* out = (float*)d_out;

    cudaFuncSetAttribute(gemm_mma_bf16x3,
                         cudaFuncAttributeMaxDynamicSharedMemorySize, GEMM_SMEM);

    __nv_bfloat16 *pWgh, *pWgl, *pWsh, *pWsl, *pxh, *pxl, *pLgh, *pLgl, *pRgh, *pRgl;
    float *pLg, *pRg, *pSim, *pZ;
    cudaGetSymbolAddress((void**)&pWgh, g_Wgt_h);
    cudaGetSymbolAddress((void**)&pWgl, g_Wgt_l);
    cudaGetSymbolAddress((void**)&pWsh, g_Wst_h);
    cudaGetSymbolAddress((void**)&pWsl, g_Wst_l);
    cudaGetSymbolAddress((void**)&pxh,  g_xh);
    cudaGetSymbolAddress((void**)&pxl,  g_xl);
    cudaGetSymbolAddress((void**)&pLg,  g_Lg);
    cudaGetSymbolAddress((void**)&pRg,  g_Rg);
    cudaGetSymbolAddress((void**)&pLgh, g_Lgh);
    cudaGetSymbolAddress((void**)&pLgl, g_Lgl);
    cudaGetSymbolAddress((void**)&pRgh, g_Rgh);
    cudaGetSymbolAddress((void**)&pRgl, g_Rgl);
    cudaGetSymbolAddress((void**)&pSim, g_sim);
    cudaGetSymbolAddress((void**)&pZ,   g_z);

    dim3 tb(32, 8), tg(24, 24);
    transpose_split768<<<tg, tb>>>(Wg, pWgh, pWgl);
    for (int l = 0; l < NLAYERS; l++)
        transpose_split768<<<tg, tb>>>(Ws + (size_t)l * CC * CC,
                                       pWsh + (size_t)l * CC * CC,
                                       pWsl + (size_t)l * CC * CC);

    init_x_kernel<<<NUM_L * CC / 256, 256>>>(l_feat, r_feat);

    // GraphGenerator: Lg, Rg, sim, top-k
    gemm_mma_bf16x3<<<dim3(CC / 128, NUM_L / 128), 256, GEMM_SMEM>>>(
        pxh, pxl, pWgh, pWgl, pLg, NUM_L, CC, CC);
    gemm_mma_bf16x3<<<dim3(CC / 128, NUM_L / 128), 256, GEMM_SMEM>>>(
        pxh + (size_t)NUM_L * CC, pxl + (size_t)NUM_L * CC, pWgh, pWgl, pRg, NUM_L, CC, CC);
    split_kernel<<<NUM_L * CC / 256, 256>>>(pLg, pLgh, pLgl, NUM_L * CC);
    split_kernel<<<NUM_L * CC / 256, 256>>>(pRg, pRgh, pRgl, NUM_L * CC);
    gemm_mma_bf16x3<<<dim3(NUM_L / 128, NUM_L / 128), 256, GEMM_SMEM>>>(
        pLgh, pLgl, pRgh, pRgl, pSim, NUM_L, NUM_L, CC);
    topk8_kernel<<<NUM_L, 256>>>();

    // CSR for graph 1
    zero_deg_kernel<<<16, 256>>>();
    count_deg_kernel<<<NUM_L * KSEL / 256, 256>>>();
    scan_off_kernel<<<1, 512>>>();
    init_cursor_kernel<<<16, 256>>>();
    fill_atomic_kernel<<<NUM_L * KSEL / 256, 256>>>();
    sort_convert_kernel<<<16, 256>>>();

    for (int g = 0; g < 2; g++) {
        for (int l = 0; l < NLAYERS; l++) {
            gemm_mma_bf16x3<<<dim3(CC / 128, NTOT / 128), 256, GEMM_SMEM>>>(
                pxh, pxl, pWsh + (size_t)l * CC * CC, pWsl + (size_t)l * CC * CC,
                pZ, NTOT, CC, CC);
            elr_kernel<<<NTOT, 384>>>(a_src + l * HH * DDIM, a_dst + l * HH * DDIM);
            if (g == 0) agg1_kernel<<<NTOT, 256>>>();
            else        agg2_kernel<<<NTOT, 256>>>();
            act_kernel<<<NTOT * CC / 256, 256>>>(b + l * CC, (l < NLAYERS - 1) ? 1 : 0);
        }
    }
    extract_kernel<<<96, 256>>>(out);
}

// round 7
// speedup vs baseline: 2.8543x; 1.0669x over previous
#include <cuda_runtime.h>
#include <cuda_bf16.h>
#include <math.h>
#include <stdint.h>

#define NUM_L   4096
#define NTOT    8192
#define CC      768
#define HH      12
#define DDIM    64
#define KSEL    8
#define PPAT    256
#define NLAYERS 4
#define NEG_SLOPE 0.2f

// ---------------- device scratch (static: no allocation allowed) ----------------
__device__ float g_sim[NUM_L * NUM_L];          // 64 MB
__device__ int   g_idx[NUM_L * KSEL];
__device__ float g_x [NTOT * CC];
__device__ float g_z [NTOT * CC];
__device__ float g_el[NTOT * HH];
__device__ float g_er[NTOT * HH];
__device__ float g_Lg[NUM_L * CC];
__device__ float g_Rg[NUM_L * CC];
__device__ __nv_bfloat16 g_xh[NTOT * CC], g_xl[NTOT * CC];
__device__ __nv_bfloat16 g_Wgt_h[CC * CC], g_Wgt_l[CC * CC];
__device__ __nv_bfloat16 g_Wst_h[NLAYERS * CC * CC], g_Wst_l[NLAYERS * CC * CC];
__device__ __nv_bfloat16 g_Lgh[NUM_L * CC], g_Lgl[NUM_L * CC];
__device__ __nv_bfloat16 g_Rgh[NUM_L * CC], g_Rgl[NUM_L * CC];
__device__ int   g_deg[NUM_L];
__device__ int   g_off[NUM_L + 1];
__device__ int   g_elist[NUM_L * KSEL];

__device__ __forceinline__ float lrelu(float x) { return x >= 0.f ? x : NEG_SLOPE * x; }

__device__ __forceinline__ uint32_t smem_u32(const void* p) {
    uint32_t a;
    asm("{ .reg .u64 t; cvta.to.shared.u64 t, %1; cvt.u32.u64 %0, t; }" : "=r"(a) : "l"(p));
    return a;
}

// ======================= mma.sync bf16x3 GEMM =======================
// C[M,N] = fp32(A) * fp32(B)^T.  A,B as bf16 (hi,lo) pairs, K-contiguous rows.
// CTA tile 128x128, 256 thr (8 warps, 2x4), warp tile 64x32, K-chunk 32, 3 stages.
#define SA      40                      // smem row stride in bf16 (80 B, ldmatrix conflict-free)
#define TILE_B  (128 * SA * 2)          // 10240 B per 128x32 tile
#define STAGE_B (4 * TILE_B)            // Ah, Al, Bh, Bl = 40960 B
#define NSTAGE  3
#define GEMM_SMEM (NSTAGE * STAGE_B)    // 122880 B

#define CP16(s, g) \
    asm volatile("cp.async.cg.shared.global [%0], [%1], 16;" :: "r"(s), "l"(g))
#define CP_COMMIT() asm volatile("cp.async.commit_group;" ::: "memory")
#define CP_WAIT1()  asm volatile("cp.async.wait_group 1;" ::: "memory")

#define LDSM4(r0, r1, r2, r3, a) \
    asm volatile("ldmatrix.sync.aligned.m8n8.x4.shared.b16 {%0,%1,%2,%3}, [%4];" \
                 : "=r"(r0), "=r"(r1), "=r"(r2), "=r"(r3) : "r"(a))

#define MMA16816(d, a, b) \
    asm volatile("mma.sync.aligned.m16n8k16.row.col.f32.bf16.bf16.f32 " \
                 "{%0,%1,%2,%3},{%4,%5,%6,%7},{%8,%9},{%0,%1,%2,%3};" \
                 : "+f"((d)[0]), "+f"((d)[1]), "+f"((d)[2]), "+f"((d)[3]) \
                 : "r"((a)[0]), "r"((a)[1]), "r"((a)[2]), "r"((a)[3]), \
                   "r"((b)[0]), "r"((b)[1]))

__global__ void __launch_bounds__(256, 1) gemm_mma_bf16x3(
    const __nv_bfloat16* __restrict__ Ah, const __nv_bfloat16* __restrict__ Al,
    const __nv_bfloat16* __restrict__ Bh, const __nv_bfloat16* __restrict__ Bl,
    float* __restrict__ C, int M, int N, int K)
{
    extern __shared__ __align__(16) char dsm[];
    const uint32_t sbase = smem_u32(dsm);
    const int tid = threadIdx.x;
    const int wid = tid >> 5, lane = tid & 31;
    const int wm = wid & 1, wn = wid >> 1;          // 2 x 4 warp grid
    const int bm = blockIdx.y * 128, bn = blockIdx.x * 128;

    const __nv_bfloat16* srcs[4] = {
        Ah + (size_t)bm * K, Al + (size_t)bm * K,
        Bh + (size_t)bn * K, Bl + (size_t)bn * K };

    // per-thread load mapping: 2 segments of 16B per tile per stage
    const int r0 = tid >> 2, c0 = tid & 3;          // seg 0: row, 16B-col
    const int r1 = (tid + 256) >> 2, c1 = (tid + 256) & 3;

    // ldmatrix per-thread offsets
    const int lj = lane >> 3, lr = lane & 7;
    const uint32_t aoff = (uint32_t)((((lj & 1) * 8 + lr) * SA + (lj >> 1) * 8) * 2);
    const uint32_t boff = (uint32_t)((((lj >> 1) * 8 + lr) * SA + (lj & 1) * 8) * 2);

    float acc[4][4][4];
#pragma unroll
    for (int i = 0; i < 4; i++)
#pragma unroll
        for (int j = 0; j < 4; j++)
#pragma unroll
            for (int k = 0; k < 4; k++) acc[i][j][k] = 0.f;

    const int nc = K >> 5;                          // K-chunks of 32

    // prologue: stages 0 and 1
#pragma unroll
    for (int s = 0; s < NSTAGE - 1; s++) {
        const uint32_t st = sbase + s * STAGE_B;
        const int kb = s * 32;
#pragma unroll
        for (int t = 0; t < 4; t++) {
            const __nv_bfloat16* gp = srcs[t] + kb;
            CP16(st + t * TILE_B + r0 * (SA * 2) + c0 * 16, gp + (size_t)r0 * K + c0 * 8);
            CP16(st + t * TILE_B + r1 * (SA * 2) + c1 * 16, gp + (size_t)r1 * K + c1 * 8);
        }
        CP_COMMIT();
    }

    for (int c = 0; c < nc; c++) {
        CP_WAIT1();
        __syncthreads();
        // issue loads for stage c+2 into buffer (c+2)%3 (freed: all warps passed
        // the sync above only after finishing compute on stage c-1 = same buffer)
        if (c + NSTAGE - 1 < nc) {
            const uint32_t st2 = sbase + ((c + NSTAGE - 1) % NSTAGE) * STAGE_B;
            const int kb = (c + NSTAGE - 1) * 32;
#pragma unroll
            for (int t = 0; t < 4; t++) {
                const __nv_bfloat16* gp = srcs[t] + kb;
                CP16(st2 + t * TILE_B + r0 * (SA * 2) + c0 * 16, gp + (size_t)r0 * K + c0 * 8);
                CP16(st2 + t * TILE_B + r1 * (SA * 2) + c1 * 16, gp + (size_t)r1 * K + c1 * 8);
            }
        }
        CP_COMMIT();

        const uint32_t st = sbase + (c % NSTAGE) * STAGE_B;
        const uint32_t sAh = st + 0 * TILE_B + (uint32_t)(wm * 64 * SA * 2);
        const uint32_t sAl = st + 1 * TILE_B + (uint32_t)(wm * 64 * SA * 2);
        const uint32_t sBh = st + 2 * TILE_B + (uint32_t)(wn * 32 * SA * 2);
        const uint32_t sBl = st + 3 * TILE_B + (uint32_t)(wn * 32 * SA * 2);
#pragma unroll
        for (int kk = 0; kk < 2; kk++) {
            uint32_t ah[4][4], al[4][4], bh[2][4], bl[2][4];
            const uint32_t kadd = kk * 32;          // kk*16 elems * 2 B
#pragma unroll
            for (int mt = 0; mt < 4; mt++) {
                const uint32_t moff = (uint32_t)(mt * 16 * SA * 2) + kadd;
                LDSM4(ah[mt][0], ah[mt][1], ah[mt][2], ah[mt][3], sAh + moff + aoff);
                LDSM4(al[mt][0], al[mt][1], al[mt][2], al[mt][3], sAl + moff + aoff);
            }
#pragma unroll
            for (int np = 0; np < 2; np++) {
                const uint32_t noff = (uint32_t)(np * 16 * SA * 2) + kadd;
                LDSM4(bh[np][0], bh[np][1], bh[np][2], bh[np][3], sBh + noff + boff);
                LDSM4(bl[np][0], bl[np][1], bl[np][2], bl[np][3], sBl + noff + boff);
            }
#pragma unroll
            for (int mt = 0; mt < 4; mt++)
#pragma unroll
                for (int nt = 0; nt < 4; nt++) {
                    const uint32_t* bhf = &bh[nt >> 1][(nt & 1) * 2];
                    const uint32_t* blf = &bl[nt >> 1][(nt & 1) * 2];
                    MMA16816(acc[mt][nt], ah[mt], bhf);
                    MMA16816(acc[mt][nt], ah[mt], blf);
                    MMA16816(acc[mt][nt], al[mt], bhf);
                }
        }
    }

    // epilogue
    const int er = lane >> 2, ec = (lane & 3) * 2;
#pragma unroll
    for (int mt = 0; mt < 4; mt++) {
        const int row = bm + wm * 64 + mt * 16 + er;
#pragma unroll
        for (int nt = 0; nt < 4; nt++) {
            const int col = bn + wn * 32 + nt * 8 + ec;
            float2* p0 = (float2*)(C + (size_t)row * N + col);
            float2* p1 = (float2*)(C + (size_t)(row + 8) * N + col);
            *p0 = make_float2(acc[mt][nt][0], acc[mt][nt][1]);
            *p1 = make_float2(acc[mt][nt][2], acc[mt][nt][3]);
        }
    }
}

// ======================= fp32 -> bf16 hi/lo split =======================
__device__ __forceinline__ void split2(float v, __nv_bfloat16& h, __nv_bfloat16& l) {
    h = __float2bfloat16(v);
    l = __float2bfloat16(v - __bfloat162float(h));
}
__global__ void split_kernel(const float* __restrict__ src, __nv_bfloat16* __restrict__ h,
                             __nv_bfloat16* __restrict__ l, int n) {
    int i = blockIdx.x * 256 + threadIdx.x;
    if (i < n) split2(src[i], h[i], l[i]);
}

// ---------------- 768x768 transpose + split ----------------
__global__ void transpose_split768(const float* __restrict__ src,
                                   __nv_bfloat16* __restrict__ dh,
                                   __nv_bfloat16* __restrict__ dl) {
    __shared__ float t[32][33];
    int bx = blockIdx.x * 32, by = blockIdx.y * 32;
    int x = bx + threadIdx.x;
#pragma unroll
    for (int j = 0; j < 32; j += 8)
        t[threadIdx.y + j][threadIdx.x] = src[(size_t)(by + threadIdx.y + j) * CC + x];
    __syncthreads();
    int x2 = by + threadIdx.x;
#pragma unroll
    for (int j = 0; j < 32; j += 8) {
        float v = t[threadIdx.x][threadIdx.y + j];
        size_t o = (size_t)(bx + threadIdx.y + j) * CC + x2;
        __nv_bfloat16 h, l; split2(v, h, l);
        dh[o] = h; dl[o] = l;
    }
}

// ---------------- top-8 per row of sim ----------------
__global__ __launch_bounds__(256) void topk8_kernel() {
    __shared__ float sv[NUM_L];
    __shared__ float rv[256];
    __shared__ int   ri[256];
    int r = blockIdx.x, tid = threadIdx.x;
    const float* row = g_sim + (size_t)r * NUM_L;
    for (int c = tid; c < NUM_L; c += 256) sv[c] = row[c];
    __syncthreads();
    for (int t = 0; t < KSEL; t++) {
        float bv = -INFINITY; int bi = NUM_L;
        for (int c = tid; c < NUM_L; c += 256) {
            float v = sv[c];
            if (v > bv || (v == bv && c < bi)) { bv = v; bi = c; }
        }
        rv[tid] = bv; ri[tid] = bi;
        __syncthreads();
        for (int s = 128; s > 0; s >>= 1) {
            if (tid < s) {
                float v = rv[tid + s]; int i2 = ri[tid + s];
                if (v > rv[tid] || (v == rv[tid] && i2 < ri[tid])) { rv[tid] = v; ri[tid] = i2; }
            }
            __syncthreads();
        }
        if (tid == 0) { g_idx[r * KSEL + t] = ri[0]; sv[ri[0]] = -INFINITY; }
        __syncthreads();
    }
}

// ---------------- CSR build (dst-grouped; edge order restored by sort) ---------
__global__ void zero_deg_kernel() {
    int i = blockIdx.x * 256 + threadIdx.x;
    if (i < NUM_L) g_deg[i] = 0;
}
__global__ void count_deg_kernel() {
    int e = blockIdx.x * 256 + threadIdx.x;
    if (e < NUM_L * KSEL) atomicAdd(&g_deg[g_idx[e]], 1);
}
__global__ __launch_bounds__(512) void scan_off_kernel() {
    __shared__ int ss[512];
    int tid = threadIdx.x;
    int base = tid * 8;
    int loc[8]; int s = 0;
#pragma unroll
    for (int i = 0; i < 8; i++) { loc[i] = s; s += g_deg[base + i]; }
    ss[tid] = s; __syncthreads();
    for (int d = 1; d < 512; d <<= 1) {
        int v = (tid >= d) ? ss[tid - d] : 0;
        __syncthreads();
        ss[tid] += v;
        __syncthreads();
    }
    int excl = ss[tid] - s;
#pragma unroll
    for (int i = 0; i < 8; i++) g_off[base + i] = excl + loc[i];
    if (tid == 511) g_off[NUM_L] = ss[511];
}
__global__ void init_cursor_kernel() {
    int i = blockIdx.x * 256 + threadIdx.x;
    if (i < NUM_L) g_deg[i] = g_off[i];
}
__global__ void fill_atomic_kernel() {
    int e = blockIdx.x * 256 + threadIdx.x;
    if (e < NUM_L * KSEL) {
        int pos = atomicAdd(&g_deg[g_idx[e]], 1);
        g_elist[pos] = e;                 // store edge index; sorted below
    }
}
__global__ void sort_convert_kernel() {
    int j = blockIdx.x * 256 + threadIdx.x;
    if (j >= NUM_L) return;
    int e0 = g_off[j], e1 = g_off[j + 1];
    for (int i = e0 + 1; i < e1; i++) {   // insertion sort by edge index (deterministic)
        int key = g_elist[i];
        int k = i - 1;
        while (k >= e0 && g_elist[k] > key) { g_elist[k + 1] = g_elist[k]; k--; }
        g_elist[k + 1] = key;
    }
    for (int i = e0; i < e1; i++) g_elist[i] >>= 3;   // edge -> src left node
}

// ---------------- x init: concat(node_l, node_r) + split ----------------
__global__ void init_x_kernel(const float* __restrict__ l, const float* __restrict__ r) {
    int i = blockIdx.x * 256 + threadIdx.x;
    if (i < NUM_L * CC) {
        float a = l[i], b = r[i];
        g_x[i] = a; g_x[NUM_L * CC + i] = b;
        split2(a, g_xh[i], g_xl[i]);
        split2(b, g_xh[NUM_L * CC + i], g_xl[NUM_L * CC + i]);
    }
}

// ---------------- el/er ----------------
__global__ __launch_bounds__(384) void elr_kernel(const float* __restrict__ as,
                                                  const float* __restrict__ ad) {
    int n = blockIdx.x;
    int w = threadIdx.x >> 5, lane = threadIdx.x & 31;
    const float* zr = g_z + (size_t)n * CC + w * DDIM;
    float z0 = zr[lane], z1 = zr[lane + 32];
    float sl = z0 * as[w * DDIM + lane] + z1 * as[w * DDIM + lane + 32];
    float sr = z0 * ad[w * DDIM + lane] + z1 * ad[w * DDIM + lane + 32];
#pragma unroll
    for (int o = 16; o; o >>= 1) {
        sl += __shfl_xor_sync(0xffffffffu, sl, o);
        sr += __shfl_xor_sync(0xffffffffu, sr, o);
    }
    if (lane == 0) { g_el[n * HH + w] = sl; g_er[n * HH + w] = sr; }
}

// ---------------- fused bias + activation + split ----------------
__device__ __forceinline__ void store_out(int n, int d, float v, int elu) {
    if (elu) v = v > 0.f ? v : expm1f(v);
    size_t o = (size_t)n * CC + d;
    g_x[o] = v;
    split2(v, g_xh[o], g_xl[o]);
}

// ---------------- 12-channel block reductions ----------------
__device__ __forceinline__ void block_max12(float* lv, float* red, float* outp, int tid) {
#pragma unroll
    for (int h = 0; h < HH; h++)
#pragma unroll
        for (int o = 16; o; o >>= 1)
            lv[h] = fmaxf(lv[h], __shfl_xor_sync(0xffffffffu, lv[h], o));
    if ((tid & 31) == 0)
#pragma unroll
        for (int h = 0; h < HH; h++) red[(tid >> 5) * HH + h] = lv[h];
    __syncthreads();
    if (tid < HH) {
        float v = red[tid];
#pragma unroll
        for (int w = 1; w < 8; w++) v = fmaxf(v, red[w * HH + tid]);
        outp[tid] = v;
    }
    __syncthreads();
}
__device__ __forceinline__ void block_sum12(float* lv, float* red, float* outp, int tid) {
#pragma unroll
    for (int h = 0; h < HH; h++)
#pragma unroll
        for (int o = 16; o; o >>= 1)
            lv[h] += __shfl_xor_sync(0xffffffffu, lv[h], o);
    if ((tid & 31) == 0)
#pragma unroll
        for (int h = 0; h < HH; h++) red[(tid >> 5) * HH + h] = lv[h];
    __syncthreads();
    if (tid < HH) {
        float v = red[tid];
#pragma unroll
        for (int w = 1; w < 8; w++) v += red[w * HH + tid];
        outp[tid] = v;
    }
    __syncthreads();
}

// ---------------- GAT aggregation + act, graph 1 ----------------
__global__ __launch_bounds__(256) void agg1_kernel(const float* __restrict__ bias, int elu) {
    int n = blockIdx.x, tid = threadIdx.x;
    if (n < NUM_L) {   // left nodes: self loop only -> out = act(z + b)
        for (int d = tid; d < CC; d += 256)
            store_out(n, d, g_z[(size_t)n * CC + d] + bias[d], elu);
        return;
    }
    __shared__ float s_er[HH], s_m[HH], s_sum[HH], s_inv[HH];
    __shared__ float red[8 * HH];
    int j = n - NUM_L;
    int e0 = g_off[j], e1 = g_off[j + 1];
    int deg = e1 - e0;
    if (tid < HH) s_er[tid] = g_er[n * HH + tid];
    __syncthreads();

    float lv[HH];
#pragma unroll
    for (int h = 0; h < HH; h++) lv[h] = -INFINITY;
    for (int t = tid; t < deg + 1; t += 256) {
        int src = (t < deg) ? g_elist[e0 + t] : n;
        const float* elp = g_el + src * HH;
#pragma unroll
        for (int h = 0; h < HH; h++) lv[h] = fmaxf(lv[h], lrelu(elp[h] + s_er[h]));
    }
    block_max12(lv, red, s_m, tid);

#pragma unroll
    for (int h = 0; h < HH; h++) lv[h] = 0.f;
    for (int t = tid; t < deg + 1; t += 256) {
        int src = (t < deg) ? g_elist[e0 + t] : n;
        const float* elp = g_el + src * HH;
#pragma unroll
        for (int h = 0; h < HH; h++) lv[h] += expf(lrelu(elp[h] + s_er[h]) - s_m[h]);
    }
    block_sum12(lv, red, s_sum, tid);
    if (tid < HH) s_inv[tid] = 1.f / s_sum[tid];
    __syncthreads();

    for (int d = tid; d < CC; d += 256) {
        int h = d >> 6;
        float m = s_m[h], inv = s_inv[h], erh = s_er[h];
        float acc = expf(lrelu(g_el[n * HH + h] + erh) - m) * inv * g_z[(size_t)n * CC + d];
        for (int e = e0; e < e1; e++) {
            int src = g_elist[e];
            acc += expf(lrelu(g_el[src * HH + h] + erh) - m) * inv * g_z[(size_t)src * CC + d];
        }
        store_out(n, d, acc + bias[d], elu);
    }
}

// ---------------- GAT aggregation + act, graph 2 ----------------
__global__ __launch_bounds__(256) void agg2_kernel(const float* __restrict__ bias,
                                                   int elu, int only_img) {
    int n = blockIdx.x, tid = threadIdx.x;
    if (n & (PPAT - 1)) {
        if (only_img) return;   // last layer: non-image outputs are never read
        for (int d = tid; d < CC; d += 256)
            store_out(n, d, g_z[(size_t)n * CC + d] + bias[d], elu);
        return;
    }
    __shared__ float s_er[HH], s_m[HH], s_sum[HH], s_inv[HH];
    __shared__ float s_w[PPAT * HH];
    __shared__ float red[8 * HH];
    if (tid < HH) s_er[tid] = g_er[n * HH + tid];
    __syncthreads();

    int src = n + tid;
    float ev[HH];
    const float* elp = g_el + src * HH;
#pragma unroll
    for (int h = 0; h < HH; h++) ev[h] = lrelu(elp[h] + s_er[h]);

    float lv[HH];
#pragma unroll
    for (int h = 0; h < HH; h++) lv[h] = ev[h];
    block_max12(lv, red, s_m, tid);

    float mult = (tid == 0) ? 2.f : 1.f;   // duplicated self edge
    float ex[HH];
#pragma unroll
    for (int h = 0; h < HH; h++) { ex[h] = expf(ev[h] - s_m[h]) * mult; lv[h] = ex[h]; }
    block_sum12(lv, red, s_sum, tid);
    if (tid < HH) s_inv[tid] = 1.f / s_sum[tid];
    __syncthreads();
#pragma unroll
    for (int h = 0; h < HH; h++) s_w[tid * HH + h] = ex[h] * s_inv[h];
    __syncthreads();

    for (int d = tid; d < CC; d += 256) {
        int h = d >> 6;
        float acc = 0.f;
        for (int i = 0; i < PPAT; i++)
            acc += s_w[i * HH + h] * g_z[(size_t)(n + i) * CC + d];
        store_out(n, d, acc + bias[d], elu);
    }
}

// ---------------- output ----------------
__global__ void extract_kernel(float* __restrict__ out) {
    int i = blockIdx.x * 256 + threadIdx.x;
    int r = i / CC, c = i % CC;
    out[i] = g_x[(size_t)(r * PPAT) * CC + c];
}

// ---------------- launch ----------------
extern "C" void kernel_launch(void* const* d_in, const int* in_sizes, int n_in,
                              void* d_out, int out_size) {
    (void)in_sizes; (void)n_in; (void)out_size;
    const float* l_feat = (const float*)d_in[0];
    const float* r_feat = (const float*)d_in[1];
    const float* Wg     = (const float*)d_in[2];
    const float* Ws     = (const float*)d_in[3];
    const float* a_src  = (const float*)d_in[4];
    const float* a_dst  = (const float*)d_in[5];
    const float* b      = (const float*)d_in[6];
    float* out = (float*)d_out;

    cudaFuncSetAttribute(gemm_mma_bf16x3,
                         cudaFuncAttributeMaxDynamicSharedMemorySize, GEMM_SMEM);

    __nv_bfloat16 *pWgh, *pWgl, *pWsh, *pWsl, *pxh, *pxl, *pLgh, *pLgl, *pRgh, *pRgl;
    float *pLg, *pRg, *pSim, *pZ;
    cudaGetSymbolAddress((void**)&pWgh, g_Wgt_h);
    cudaGetSymbolAddress((void**)&pWgl, g_Wgt_l);
    cudaGetSymbolAddress((void**)&pWsh, g_Wst_h);
    cudaGetSymbolAddress((void**)&pWsl, g_Wst_l);
    cudaGetSymbolAddress((void**)&pxh,  g_xh);
    cudaGetSymbolAddress((void**)&pxl,  g_xl);
    cudaGetSymbolAddress((void**)&pLg,  g_Lg);
    cudaGetSymbolAddress((void**)&pRg,  g_Rg);
    cudaGetSymbolAddress((void**)&pLgh, g_Lgh);
    cudaGetSymbolAddress((void**)&pLgl, g_Lgl);
    cudaGetSymbolAddress((void**)&pRgh, g_Rgh);
    cudaGetSymbolAddress((void**)&pRgl, g_Rgl);
    cudaGetSymbolAddress((void**)&pSim, g_sim);
    cudaGetSymbolAddress((void**)&pZ,   g_z);

    dim3 tb(32, 8), tg(24, 24);
    transpose_split768<<<tg, tb>>>(Wg, pWgh, pWgl);
    for (int l = 0; l < NLAYERS; l++)
        transpose_split768<<<tg, tb>>>(Ws + (size_t)l * CC * CC,
                                       pWsh + (size_t)l * CC * CC,
                                       pWsl + (size_t)l * CC * CC);

    init_x_kernel<<<NUM_L * CC / 256, 256>>>(l_feat, r_feat);

    // GraphGenerator: Lg, Rg, sim, top-k
    gemm_mma_bf16x3<<<dim3(CC / 128, NUM_L / 128), 256, GEMM_SMEM>>>(
        pxh, pxl, pWgh, pWgl, pLg, NUM_L, CC, CC);
    gemm_mma_bf16x3<<<dim3(CC / 128, NUM_L / 128), 256, GEMM_SMEM>>>(
        pxh + (size_t)NUM_L * CC, pxl + (size_t)NUM_L * CC, pWgh, pWgl, pRg, NUM_L, CC, CC);
    split_kernel<<<NUM_L * CC / 256, 256>>>(pLg, pLgh, pLgl, NUM_L * CC);
    split_kernel<<<NUM_L * CC / 256, 256>>>(pRg, pRgh, pRgl, NUM_L * CC);
    gemm_mma_bf16x3<<<dim3(NUM_L / 128, NUM_L / 128), 256, GEMM_SMEM>>>(
        pLgh, pLgl, pRgh, pRgl, pSim, NUM_L, NUM_L, CC);
    topk8_kernel<<<NUM_L, 256>>>();

    // CSR for graph 1
    zero_deg_kernel<<<16, 256>>>();
    count_deg_kernel<<<NUM_L * KSEL / 256, 256>>>();
    scan_off_kernel<<<1, 512>>>();
    init_cursor_kernel<<<16, 256>>>();
    fill_atomic_kernel<<<NUM_L * KSEL / 256, 256>>>();
    sort_convert_kernel<<<16, 256>>>();

    for (int g = 0; g < 2; g++) {
        for (int l = 0; l < NLAYERS; l++) {
            gemm_mma_bf16x3<<<dim3(CC / 128, NTOT / 128), 256, GEMM_SMEM>>>(
                pxh, pxl, pWsh + (size_t)l * CC * CC, pWsl + (size_t)l * CC * CC,
                pZ, NTOT, CC, CC);
            elr_kernel<<<NTOT, 384>>>(a_src + l * HH * DDIM, a_dst + l * HH * DDIM);
            int elu = (l < NLAYERS - 1) ? 1 : 0;
            if (g == 0) agg1_kernel<<<NTOT, 256>>>(b + l * CC, elu);
            else        agg2_kernel<<<NTOT, 256>>>(b + l * CC, elu,
                                                   (l == NLAYERS - 1) ? 1 : 0);
        }
    }
    extract_kernel<<<96, 256>>>(out);
}

// round 8
// speedup vs baseline: 3.0845x; 1.0806x over previous
#include <cuda_runtime.h>
#include <cuda_bf16.h>
#include <math.h>
#include <stdint.h>

#define NUM_L   4096
#define NTOT    8192
#define CC      768
#define HH      12
#define DDIM    64
#define KSEL    8
#define PPAT    256
#define NLAYERS 4
#define NEG_SLOPE 0.2f

// ---------------- device scratch ----------------
__device__ float g_sim[NUM_L * NUM_L];          // 64 MB
__device__ int   g_idx[NUM_L * KSEL];
__device__ float g_z [NTOT * CC];
__device__ float g_el[NTOT * HH];
__device__ float g_er[NTOT * HH];
__device__ __nv_bfloat16 g_xh[NTOT * CC], g_xl[NTOT * CC];
__device__ __nv_bfloat16 g_LRh[NTOT * CC], g_LRl[NTOT * CC];
__device__ __nv_bfloat16 g_Wgt_h[CC * CC], g_Wgt_l[CC * CC];
__device__ __nv_bfloat16 g_Wst_h[NLAYERS * CC * CC], g_Wst_l[NLAYERS * CC * CC];
__device__ int   g_deg[NUM_L];
__device__ int   g_off[NUM_L + 1];
__device__ int   g_elist[NUM_L * KSEL];

__device__ __forceinline__ float lrelu(float x) { return x >= 0.f ? x : NEG_SLOPE * x; }

__device__ __forceinline__ uint32_t smem_u32(const void* p) {
    uint32_t a;
    asm("{ .reg .u64 t; cvta.to.shared.u64 t, %1; cvt.u32.u64 %0, t; }" : "=r"(a) : "l"(p));
    return a;
}
__device__ __forceinline__ void split2(float v, __nv_bfloat16& h, __nv_bfloat16& l) {
    h = __float2bfloat16(v);
    l = __float2bfloat16(v - __bfloat162float(h));
}

// ======================= mma.sync bf16x3 GEMM =======================
// C = fp32(A)*fp32(B)^T; A,B bf16 (hi,lo) pairs, K-contiguous rows.
// CTA 128x128, 256 thr (2x4 warps, warp tile 64x32), K-chunk 32, 2 stages, 2 CTA/SM.
#define SA      40
#define TILE_B  (128 * SA * 2)          // 10240 B per 128x32 tile
#define STAGE_B (4 * TILE_B)            // 40960 B
#define NSTAGE  2
#define GEMM_SMEM (NSTAGE * STAGE_B)    // 81920 B

#define CP16(s, g) \
    asm volatile("cp.async.cg.shared.global [%0], [%1], 16;" :: "r"(s), "l"(g))
#define CP_COMMIT() asm volatile("cp.async.commit_group;" ::: "memory")
#define CP_WAIT1()  asm volatile("cp.async.wait_group 1;" ::: "memory")

#define LDSM4(r0, r1, r2, r3, a) \
    asm volatile("ldmatrix.sync.aligned.m8n8.x4.shared.b16 {%0,%1,%2,%3}, [%4];" \
                 : "=r"(r0), "=r"(r1), "=r"(r2), "=r"(r3) : "r"(a))

#define MMA16816(d, a, b) \
    asm volatile("mma.sync.aligned.m16n8k16.row.col.f32.bf16.bf16.f32 " \
                 "{%0,%1,%2,%3},{%4,%5,%6,%7},{%8,%9},{%0,%1,%2,%3};" \
                 : "+f"((d)[0]), "+f"((d)[1]), "+f"((d)[2]), "+f"((d)[3]) \
                 : "r"((a)[0]), "r"((a)[1]), "r"((a)[2]), "r"((a)[3]), \
                   "r"((b)[0]), "r"((b)[1]))

__global__ void __launch_bounds__(256, 2) gemm_mma_bf16x3(
    const __nv_bfloat16* __restrict__ Ah, const __nv_bfloat16* __restrict__ Al,
    const __nv_bfloat16* __restrict__ Bh, const __nv_bfloat16* __restrict__ Bl,
    float* __restrict__ Cf, __nv_bfloat16* __restrict__ Ch, __nv_bfloat16* __restrict__ Cl,
    int M, int N, int K, int splitout)
{
    extern __shared__ __align__(16) char dsm[];
    const uint32_t sbase = smem_u32(dsm);
    const int tid = threadIdx.x;
    const int wid = tid >> 5, lane = tid & 31;
    const int wm = wid & 1, wn = wid >> 1;
    const int bm = blockIdx.y * 128, bn = blockIdx.x * 128;

    const __nv_bfloat16* srcs[4] = {
        Ah + (size_t)bm * K, Al + (size_t)bm * K,
        Bh + (size_t)bn * K, Bl + (size_t)bn * K };

    const int r0 = tid >> 2, c0 = tid & 3;
    const int r1 = (tid + 256) >> 2, c1 = (tid + 256) & 3;

    const int lj = lane >> 3, lr = lane & 7;
    const uint32_t aoff = (uint32_t)((((lj & 1) * 8 + lr) * SA + (lj >> 1) * 8) * 2);
    const uint32_t boff = (uint32_t)((((lj >> 1) * 8 + lr) * SA + (lj & 1) * 8) * 2);

    float acc[4][4][4];
#pragma unroll
    for (int i = 0; i < 4; i++)
#pragma unroll
        for (int j = 0; j < 4; j++)
#pragma unroll
            for (int k = 0; k < 4; k++) acc[i][j][k] = 0.f;

    const int nc = K >> 5;

    // prologue: both stages
#pragma unroll
    for (int s = 0; s < NSTAGE; s++) {
        const uint32_t st = sbase + s * STAGE_B;
        const int kb = s * 32;
#pragma unroll
        for (int t = 0; t < 4; t++) {
            const __nv_bfloat16* gp = srcs[t] + kb;
            CP16(st + t * TILE_B + r0 * (SA * 2) + c0 * 16, gp + (size_t)r0 * K + c0 * 8);
            CP16(st + t * TILE_B + r1 * (SA * 2) + c1 * 16, gp + (size_t)r1 * K + c1 * 8);
        }
        CP_COMMIT();
    }

    for (int c = 0; c < nc; c++) {
        CP_WAIT1();
        __syncthreads();
        const uint32_t st = sbase + (c & 1) * STAGE_B;
        const uint32_t sAh = st + 0 * TILE_B + (uint32_t)(wm * 64 * SA * 2);
        const uint32_t sAl = st + 1 * TILE_B + (uint32_t)(wm * 64 * SA * 2);
        const uint32_t sBh = st + 2 * TILE_B + (uint32_t)(wn * 32 * SA * 2);
        const uint32_t sBl = st + 3 * TILE_B + (uint32_t)(wn * 32 * SA * 2);
#pragma unroll
        for (int kk = 0; kk < 2; kk++) {
            const uint32_t kadd = kk * 32;
            uint32_t bh[2][4], bl[2][4];
#pragma unroll
            for (int np = 0; np < 2; np++) {
                const uint32_t noff = (uint32_t)(np * 16 * SA * 2) + kadd;
                LDSM4(bh[np][0], bh[np][1], bh[np][2], bh[np][3], sBh + noff + boff);
                LDSM4(bl[np][0], bl[np][1], bl[np][2], bl[np][3], sBl + noff + boff);
            }
#pragma unroll
            for (int mt = 0; mt < 4; mt++) {
                uint32_t ah[4], al[4];
                const uint32_t moff = (uint32_t)(mt * 16 * SA * 2) + kadd;
                LDSM4(ah[0], ah[1], ah[2], ah[3], sAh + moff + aoff);
                LDSM4(al[0], al[1], al[2], al[3], sAl + moff + aoff);
#pragma unroll
                for (int nt = 0; nt < 4; nt++) {
                    const uint32_t* bhf = &bh[nt >> 1][(nt & 1) * 2];
                    const uint32_t* blf = &bl[nt >> 1][(nt & 1) * 2];
                    MMA16816(acc[mt][nt], ah, bhf);
                    MMA16816(acc[mt][nt], ah, blf);
                    MMA16816(acc[mt][nt], al, bhf);
                }
            }
        }
        __syncthreads();
        if (c + NSTAGE < nc) {
            const int kb = (c + NSTAGE) * 32;
#pragma unroll
            for (int t = 0; t < 4; t++) {
                const __nv_bfloat16* gp = srcs[t] + kb;
                CP16(st + t * TILE_B + r0 * (SA * 2) + c0 * 16, gp + (size_t)r0 * K + c0 * 8);
                CP16(st + t * TILE_B + r1 * (SA * 2) + c1 * 16, gp + (size_t)r1 * K + c1 * 8);
            }
        }
        CP_COMMIT();
    }

    // epilogue
    const int er = lane >> 2, ec = (lane & 3) * 2;
#pragma unroll
    for (int mt = 0; mt < 4; mt++) {
        const int row = bm + wm * 64 + mt * 16 + er;
#pragma unroll
        for (int nt = 0; nt < 4; nt++) {
            const int col = bn + wn * 32 + nt * 8 + ec;
            if (!splitout) {
                float2* p0 = (float2*)(Cf + (size_t)row * N + col);
                float2* p1 = (float2*)(Cf + (size_t)(row + 8) * N + col);
                *p0 = make_float2(acc[mt][nt][0], acc[mt][nt][1]);
                *p1 = make_float2(acc[mt][nt][2], acc[mt][nt][3]);
            } else {
#pragma unroll
                for (int half = 0; half < 2; half++) {
                    const size_t o = (size_t)(row + half * 8) * N + col;
                    __nv_bfloat16 h0, l0, h1, l1;
                    split2(acc[mt][nt][half * 2 + 0], h0, l0);
                    split2(acc[mt][nt][half * 2 + 1], h1, l1);
                    __nv_bfloat162 hv; hv.x = h0; hv.y = h1;
                    __nv_bfloat162 lv2; lv2.x = l0; lv2.y = l1;
                    *(__nv_bfloat162*)(Ch + o) = hv;
                    *(__nv_bfloat162*)(Cl + o) = lv2;
                }
            }
        }
    }
}

// ---------------- 768x768 transpose + split ----------------
__global__ void transpose_split768(const float* __restrict__ src,
                                   __nv_bfloat16* __restrict__ dh,
                                   __nv_bfloat16* __restrict__ dl) {
    __shared__ float t[32][33];
    int bx = blockIdx.x * 32, by = blockIdx.y * 32;
    int x = bx + threadIdx.x;
#pragma unroll
    for (int j = 0; j < 32; j += 8)
        t[threadIdx.y + j][threadIdx.x] = src[(size_t)(by + threadIdx.y + j) * CC + x];
    __syncthreads();
    int x2 = by + threadIdx.x;
#pragma unroll
    for (int j = 0; j < 32; j += 8) {
        float v = t[threadIdx.x][threadIdx.y + j];
        size_t o = (size_t)(bx + threadIdx.y + j) * CC + x2;
        __nv_bfloat16 h, l; split2(v, h, l);
        dh[o] = h; dl[o] = l;
    }
}

// ---------------- top-8 per row of sim ----------------
__global__ __launch_bounds__(256) void topk8_kernel() {
    __shared__ float sv[NUM_L];
    __shared__ float rv[256];
    __shared__ int   ri[256];
    int r = blockIdx.x, tid = threadIdx.x;
    const float* row = g_sim + (size_t)r * NUM_L;
    for (int c = tid; c < NUM_L; c += 256) sv[c] = row[c];
    __syncthreads();
    for (int t = 0; t < KSEL; t++) {
        float bv = -INFINITY; int bi = NUM_L;
        for (int c = tid; c < NUM_L; c += 256) {
            float v = sv[c];
            if (v > bv || (v == bv && c < bi)) { bv = v; bi = c; }
        }
        rv[tid] = bv; ri[tid] = bi;
        __syncthreads();
        for (int s = 128; s > 0; s >>= 1) {
            if (tid < s) {
                float v = rv[tid + s]; int i2 = ri[tid + s];
                if (v > rv[tid] || (v == rv[tid] && i2 < ri[tid])) { rv[tid] = v; ri[tid] = i2; }
            }
            __syncthreads();
        }
        if (tid == 0) { g_idx[r * KSEL + t] = ri[0]; sv[ri[0]] = -INFINITY; }
        __syncthreads();
    }
}

// ---------------- CSR build ----------------
__global__ void zero_deg_kernel() {
    int i = blockIdx.x * 256 + threadIdx.x;
    if (i < NUM_L) g_deg[i] = 0;
}
__global__ void count_deg_kernel() {
    int e = blockIdx.x * 256 + threadIdx.x;
    if (e < NUM_L * KSEL) atomicAdd(&g_deg[g_idx[e]], 1);
}
__global__ __launch_bounds__(512) void scan_off_kernel() {
    __shared__ int ss[512];
    int tid = threadIdx.x;
    int base = tid * 8;
    int loc[8]; int s = 0;
#pragma unroll
    for (int i = 0; i < 8; i++) { loc[i] = s; s += g_deg[base + i]; }
    ss[tid] = s; __syncthreads();
    for (int d = 1; d < 512; d <<= 1) {
        int v = (tid >= d) ? ss[tid - d] : 0;
        __syncthreads();
        ss[tid] += v;
        __syncthreads();
    }
    int excl = ss[tid] - s;
#pragma unroll
    for (int i = 0; i < 8; i++) g_off[base + i] = excl + loc[i];
    if (tid == 511) g_off[NUM_L] = ss[511];
}
__global__ void init_cursor_kernel() {
    int i = blockIdx.x * 256 + threadIdx.x;
    if (i < NUM_L) g_deg[i] = g_off[i];
}
__global__ void fill_atomic_kernel() {
    int e = blockIdx.x * 256 + threadIdx.x;
    if (e < NUM_L * KSEL) {
        int pos = atomicAdd(&g_deg[g_idx[e]], 1);
        g_elist[pos] = e;
    }
}
__global__ void sort_convert_kernel() {
    int j = blockIdx.x * 256 + threadIdx.x;
    if (j >= NUM_L) return;
    int e0 = g_off[j], e1 = g_off[j + 1];
    for (int i = e0 + 1; i < e1; i++) {
        int key = g_elist[i];
        int k = i - 1;
        while (k >= e0 && g_elist[k] > key) { g_elist[k + 1] = g_elist[k]; k--; }
        g_elist[k + 1] = key;
    }
    for (int i = e0; i < e1; i++) g_elist[i] >>= 3;
}

// ---------------- x init (bf16 split only) ----------------
__global__ void init_x_kernel(const float* __restrict__ l, const float* __restrict__ r) {
    int i = blockIdx.x * 256 + threadIdx.x;
    if (i < NUM_L * CC) {
        split2(l[i], g_xh[i], g_xl[i]);
        split2(r[i], g_xh[NUM_L * CC + i], g_xl[NUM_L * CC + i]);
    }
}

// ---------------- el/er ----------------
__global__ __launch_bounds__(384) void elr_kernel(const float* __restrict__ as,
                                                  const float* __restrict__ ad) {
    int n = blockIdx.x;
    int w = threadIdx.x >> 5, lane = threadIdx.x & 31;
    const float* zr = g_z + (size_t)n * CC + w * DDIM;
    float z0 = zr[lane], z1 = zr[lane + 32];
    float sl = z0 * as[w * DDIM + lane] + z1 * as[w * DDIM + lane + 32];
    float sr = z0 * ad[w * DDIM + lane] + z1 * ad[w * DDIM + lane + 32];
#pragma unroll
    for (int o = 16; o; o >>= 1) {
        sl += __shfl_xor_sync(0xffffffffu, sl, o);
        sr += __shfl_xor_sync(0xffffffffu, sr, o);
    }
    if (lane == 0) { g_el[n * HH + w] = sl; g_er[n * HH + w] = sr; }
}

// ---------------- fused bias + act + split (writes xh/xl only) ----------------
__device__ __forceinline__ void store_x(int n, int d, float v, int elu) {
    if (elu) v = v > 0.f ? v : expm1f(v);
    size_t o = (size_t)n * CC + d;
    split2(v, g_xh[o], g_xl[o]);
}

// ---------------- 12-channel block reductions ----------------
__device__ __forceinline__ void block_max12(float* lv, float* red, float* outp, int tid) {
#pragma unroll
    for (int h = 0; h < HH; h++)
#pragma unroll
        for (int o = 16; o; o >>= 1)
            lv[h] = fmaxf(lv[h], __shfl_xor_sync(0xffffffffu, lv[h], o));
    if ((tid & 31) == 0)
#pragma unroll
        for (int h = 0; h < HH; h++) red[(tid >> 5) * HH + h] = lv[h];
    __syncthreads();
    if (tid < HH) {
        float v = red[tid];
#pragma unroll
        for (int w = 1; w < 8; w++) v = fmaxf(v, red[w * HH + tid]);
        outp[tid] = v;
    }
    __syncthreads();
}
__device__ __forceinline__ void block_sum12(float* lv, float* red, float* outp, int tid) {
#pragma unroll
    for (int h = 0; h < HH; h++)
#pragma unroll
        for (int o = 16; o; o >>= 1)
            lv[h] += __shfl_xor_sync(0xffffffffu, lv[h], o);
    if ((tid & 31) == 0)
#pragma unroll
        for (int h = 0; h < HH; h++) red[(tid >> 5) * HH + h] = lv[h];
    __syncthreads();
    if (tid < HH) {
        float v = red[tid];
#pragma unroll
        for (int w = 1; w < 8; w++) v += red[w * HH + tid];
        outp[tid] = v;
    }
    __syncthreads();
}

// ---------------- GAT aggregation + act, graph 1 ----------------
__global__ __launch_bounds__(256) void agg1_kernel(const float* __restrict__ bias, int elu) {
    int n = blockIdx.x, tid = threadIdx.x;
    if (n < NUM_L) {   // left nodes: self loop only
        for (int d = tid; d < CC; d += 256)
            store_x(n, d, g_z[(size_t)n * CC + d] + bias[d], elu);
        return;
    }
    __shared__ float s_er[HH], s_m[HH], s_sum[HH], s_inv[HH];
    __shared__ float red[8 * HH];
    int j = n - NUM_L;
    int e0 = g_off[j], e1 = g_off[j + 1];
    int deg = e1 - e0;
    if (tid < HH) s_er[tid] = g_er[n * HH + tid];
    __syncthreads();

    float lv[HH];
#pragma unroll
    for (int h = 0; h < HH; h++) lv[h] = -INFINITY;
    for (int t = tid; t < deg + 1; t += 256) {
        int src = (t < deg) ? g_elist[e0 + t] : n;
        const float* elp = g_el + src * HH;
#pragma unroll
        for (int h = 0; h < HH; h++) lv[h] = fmaxf(lv[h], lrelu(elp[h] + s_er[h]));
    }
    block_max12(lv, red, s_m, tid);

#pragma unroll
    for (int h = 0; h < HH; h++) lv[h] = 0.f;
    for (int t = tid; t < deg + 1; t += 256) {
        int src = (t < deg) ? g_elist[e0 + t] : n;
        const float* elp = g_el + src * HH;
#pragma unroll
        for (int h = 0; h < HH; h++) lv[h] += expf(lrelu(elp[h] + s_er[h]) - s_m[h]);
    }
    block_sum12(lv, red, s_sum, tid);
    if (tid < HH) s_inv[tid] = 1.f / s_sum[tid];
    __syncthreads();

    for (int d = tid; d < CC; d += 256) {
        int h = d >> 6;
        float m = s_m[h], inv = s_inv[h], erh = s_er[h];
        float acc = expf(lrelu(g_el[n * HH + h] + erh) - m) * inv * g_z[(size_t)n * CC + d];
        for (int e = e0; e < e1; e++) {
            int src = g_elist[e];
            acc += expf(lrelu(g_el[src * HH + h] + erh) - m) * inv * g_z[(size_t)src * CC + d];
        }
        store_x(n, d, acc + bias[d], elu);
    }
}

// ---------------- GAT aggregation + act, graph 2 ----------------
// final==1: write image-node results straight to `outp`, skip everything else.
__global__ __launch_bounds__(256) void agg2_kernel(const float* __restrict__ bias,
                                                   int elu, int final_, float* outp) {
    int n = blockIdx.x, tid = threadIdx.x;
    if (n & (PPAT - 1)) {
        if (final_) return;
        for (int d = tid; d < CC; d += 256)
            store_x(n, d, g_z[(size_t)n * CC + d] + bias[d], elu);
        return;
    }
    __shared__ float s_er[HH], s_m[HH], s_sum[HH], s_inv[HH];
    __shared__ float s_w[PPAT * HH];
    __shared__ float red[8 * HH];
    if (tid < HH) s_er[tid] = g_er[n * HH + tid];
    __syncthreads();

    int src = n + tid;
    float ev[HH];
    const float* elp = g_el + src * HH;
#pragma unroll
    for (int h = 0; h < HH; h++) ev[h] = lrelu(elp[h] + s_er[h]);

    float lv[HH];
#pragma unroll
    for (int h = 0; h < HH; h++) lv[h] = ev[h];
    block_max12(lv, red, s_m, tid);

    float mult = (tid == 0) ? 2.f : 1.f;   // duplicated self edge
    float ex[HH];
#pragma unroll
    for (int h = 0; h < HH; h++) { ex[h] = expf(ev[h] - s_m[h]) * mult; lv[h] = ex[h]; }
    block_sum12(lv, red, s_sum, tid);
    if (tid < HH) s_inv[tid] = 1.f / s_sum[tid];
    __syncthreads();
#pragma unroll
    for (int h = 0; h < HH; h++) s_w[tid * HH + h] = ex[h] * s_inv[h];
    __syncthreads();

    for (int d = tid; d < CC; d += 256) {
        int h = d >> 6;
        float acc = 0.f;
        for (int i = 0; i < PPAT; i++)
            acc += s_w[i * HH + h] * g_z[(size_t)(n + i) * CC + d];
        float v = acc + bias[d];
        if (final_) {
            if (elu) v = v > 0.f ? v : expm1f(v);
            outp[(size_t)(n / PPAT) * CC + d] = v;
        } else {
            store_x(n, d, v, elu);
        }
    }
}

// ---------------- launch ----------------
extern "C" void kernel_launch(void* const* d_in, const int* in_sizes, int n_in,
                              void* d_out, int out_size) {
    (void)in_sizes; (void)n_in; (void)out_size;
    const float* l_feat = (const float*)d_in[0];
    const float* r_feat = (const float*)d_in[1];
    const float* Wg     = (const float*)d_in[2];
    const float* Ws     = (const float*)d_in[3];
    const float* a_src  = (const float*)d_in[4];
    const float* a_dst  = (const float*)d_in[5];
    const float* b      = (const float*)d_in[6];
    float* out = (float*)d_out;

    cudaFuncSetAttribute(gemm_mma_bf16x3,
                         cudaFuncAttributeMaxDynamicSharedMemorySize, GEMM_SMEM);

    __nv_bfloat16 *pWgh, *pWgl, *pWsh, *pWsl, *pxh, *pxl, *pLRh, *pLRl;
    float *pSim, *pZ;
    cudaGetSymbolAddress((void**)&pWgh, g_Wgt_h);
    cudaGetSymbolAddress((void**)&pWgl, g_Wgt_l);
    cudaGetSymbolAddress((void**)&pWsh, g_Wst_h);
    cudaGetSymbolAddress((void**)&pWsl, g_Wst_l);
    cudaGetSymbolAddress((void**)&pxh,  g_xh);
    cudaGetSymbolAddress((void**)&pxl,  g_xl);
    cudaGetSymbolAddress((void**)&pLRh, g_LRh);
    cudaGetSymbolAddress((void**)&pLRl, g_LRl);
    cudaGetSymbolAddress((void**)&pSim, g_sim);
    cudaGetSymbolAddress((void**)&pZ,   g_z);

    dim3 tb(32, 8), tg(24, 24);
    transpose_split768<<<tg, tb>>>(Wg, pWgh, pWgl);
    for (int l = 0; l < NLAYERS; l++)
        transpose_split768<<<tg, tb>>>(Ws + (size_t)l * CC * CC,
                                       pWsh + (size_t)l * CC * CC,
                                       pWsl + (size_t)l * CC * CC);

    init_x_kernel<<<NUM_L * CC / 256, 256>>>(l_feat, r_feat);

    // GraphGenerator: LR projection (merged, split-output), sim, top-k
    gemm_mma_bf16x3<<<dim3(CC / 128, NTOT / 128), 256, GEMM_SMEM>>>(
        pxh, pxl, pWgh, pWgl, nullptr, pLRh, pLRl, NTOT, CC, CC, 1);
    gemm_mma_bf16x3<<<dim3(NUM_L / 128, NUM_L / 128), 256, GEMM_SMEM>>>(
        pLRh, pLRl, pLRh + (size_t)NUM_L * CC, pLRl + (size_t)NUM_L * CC,
        pSim, nullptr, nullptr, NUM_L, NUM_L, CC, 0);
    topk8_kernel<<<NUM_L, 256>>>();

    // CSR for graph 1
    zero_deg_kernel<<<16, 256>>>();
    count_deg_kernel<<<NUM_L * KSEL / 256, 256>>>();
    scan_off_kernel<<<1, 512>>>();
    init_cursor_kernel<<<16, 256>>>();
    fill_atomic_kernel<<<NUM_L * KSEL / 256, 256>>>();
    sort_convert_kernel<<<16, 256>>>();

    for (int g = 0; g < 2; g++) {
        for (int l = 0; l < NLAYERS; l++) {
            gemm_mma_bf16x3<<<dim3(CC / 128, NTOT / 128), 256, GEMM_SMEM>>>(
                pxh, pxl, pWsh + (size_t)l * CC * CC, pWsl + (size_t)l * CC * CC,
                pZ, nullptr, nullptr, NTOT, CC, CC, 0);
            elr_kernel<<<NTOT, 384>>>(a_src + l * HH * DDIM, a_dst + l * HH * DDIM);
            int elu = (l < NLAYERS - 1) ? 1 : 0;
            if (g == 0) agg1_kernel<<<NTOT, 256>>>(b + l * CC, elu);
            else        agg2_kernel<<<NTOT, 256>>>(b + l * CC, elu,
                                                   (l == NLAYERS - 1) ? 1 : 0, out);
        }
    }
}